// round 5
// baseline (speedup 1.0000x reference)
#include <cuda_runtime.h>
#include <math.h>
#include <stdint.h>

#define BB 4
#define C 96
#define H 128
#define W 128
#define HW (H*W)          // 16384
#define KKc 9
#define CK (C*KKc)        // 864
#define NPIX (BB*HW)      // 65536 per channel
#define NTOT NPIX         // GEMM N (batch folded)

typedef unsigned long long ull;

// ---------------- device scratch (no allocations allowed) ----------------
__device__ float  g_col [ (size_t)CK * NTOT ];      // 226.5 MB deform-col [k][n]
__device__ float  g_At  [ CK * C ];                 // A transposed [k][m]
__device__ ull    g_wtp [ CK * 14 ];                // offset|mask weights, opair-packed
__device__ float4 g_wts [ (size_t)BB * KKc * HW ];  // bilinear weights (mask folded)
__device__ int4   g_idx [ (size_t)BB * KKc * HW ];  // bilinear gather indices
__device__ float  g_conv[ (size_t)C * NTOT ];       // deform-conv output [c][n]
__device__ float  g_act [ (size_t)BB * C * HW ];    // post BN+leakyrelu (NCHW)
__device__ float  g_stats[ 2 * C ];                 // mean | rstd

// packed f32x2 FMA (FFMA2) — only reachable via explicit PTX on sm_10x
#define FMA2(d, a, b) \
    asm("fma.rn.f32x2 %0, %1, %2, %0;" : "+l"(d) : "l"(a), "l"(b))

__device__ __forceinline__ ull bcast2(float v) {
    ull r;
    unsigned int u = __float_as_uint(v);
    asm("mov.b64 %0, {%1, %1};" : "=l"(r) : "r"(u));
    return r;
}

__device__ __forceinline__ unsigned smem_u32(const void* p) {
    return (unsigned)__cvta_generic_to_shared(p);
}
#define CP16(dst, src) \
    asm volatile("cp.async.ca.shared.global [%0], [%1], 16;" :: "r"(dst), "l"(src))
#define CP_COMMIT() asm volatile("cp.async.commit_group;")
#define CP_WAIT1()  asm volatile("cp.async.wait_group 1;")

// ---------------- weight prep ----------------
__global__ void wprep_kernel(const float* __restrict__ offw,
                             const float* __restrict__ modw,
                             ull* __restrict__ wtp) {
    int t = blockIdx.x * blockDim.x + threadIdx.x;   // ck*14 + j
    if (t >= CK * 14) return;
    int ck = t / 14, j = t - ck * 14;
    int o0 = 2 * j, o1 = 2 * j + 1;
    float a = (o0 < 18) ? offw[o0 * CK + ck] : modw[(o0 - 18) * CK + ck];
    float b = 0.f;
    if (o1 < 27)
        b = (o1 < 18) ? offw[o1 * CK + ck] : modw[(o1 - 18) * CK + ck];
    float2 p = make_float2(a, b);
    wtp[t] = *reinterpret_cast<ull*>(&p);
}

__global__ void atrans_kernel(const float* __restrict__ A, float* __restrict__ At) {
    int t = blockIdx.x * blockDim.x + threadIdx.x;   // k*96 + m
    if (t >= CK * C) return;
    int k = t / C, m = t - k * C;
    At[t] = A[m * CK + k];
}

// ---------------------------------------------------------------------------
// Direct 3x3 conv producing 27 outputs/pixel + bilinear-table epilogue.
// 256 threads = 4 channel-groups (24 ch each) x 64 pixel-columns x 2 rows.
// ---------------------------------------------------------------------------
__global__ void __launch_bounds__(256) offconv_kernel(
    const ull* __restrict__ wtp,     // [864][14] packed pairs
    const float* __restrict__ X,     // [B][C][H][W]
    const float* __restrict__ off_b, // [18]
    const float* __restrict__ mod_b, // [9]
    float4* __restrict__ wts,
    int4*  __restrict__ idx)
{
    __shared__ ull red[3][64][28];

    int tid  = threadIdx.x;
    int lane = tid & 63;
    int grp  = tid >> 6;
    int half = blockIdx.x & 1;
    int h0   = (blockIdx.x >> 1) * 2;
    int b    = blockIdx.y;
    int pix  = half * 64 + lane;

    const float* Xb = X + (size_t)b * C * HW;

    ull acc[2][14];
    #pragma unroll
    for (int r = 0; r < 2; r++)
        #pragma unroll
        for (int j = 0; j < 14; j++) acc[r][j] = 0ull;

    bool xm_ok = (pix > 0);
    bool xp_ok = (pix < W - 1);

    int c0 = grp * 24;
    for (int ci = 0; ci < 24; ci++) {
        int c = c0 + ci;
        ull tb[4][3];
        #pragma unroll
        for (int rr = 0; rr < 4; rr++) {
            int y = h0 - 1 + rr;
            bool yok = (y >= 0) && (y < H);
            const float* row = Xb + (size_t)c * HW + y * W + pix;
            float vm = (yok && xm_ok) ? row[-1] : 0.f;
            float v0 = yok ? row[0] : 0.f;
            float vp = (yok && xp_ok) ? row[1] : 0.f;
            tb[rr][0] = bcast2(vm);
            tb[rr][1] = bcast2(v0);
            tb[rr][2] = bcast2(vp);
        }
        const ulonglong2* wrow =
            reinterpret_cast<const ulonglong2*>(wtp + (size_t)c * 9 * 14);
        #pragma unroll
        for (int ky = 0; ky < 3; ky++) {
            #pragma unroll
            for (int kx = 0; kx < 3; kx++) {
                int tap = ky * 3 + kx;
                ull t0 = tb[ky][kx];
                ull t1 = tb[ky + 1][kx];
                #pragma unroll
                for (int j2 = 0; j2 < 7; j2++) {
                    ulonglong2 wv = wrow[tap * 7 + j2];
                    FMA2(acc[0][2 * j2],     wv.x, t0);
                    FMA2(acc[1][2 * j2],     wv.x, t1);
                    FMA2(acc[0][2 * j2 + 1], wv.y, t0);
                    FMA2(acc[1][2 * j2 + 1], wv.y, t1);
                }
            }
        }
    }

    if (grp > 0) {
        #pragma unroll
        for (int r = 0; r < 2; r++)
            #pragma unroll
            for (int j = 0; j < 14; j++)
                red[grp - 1][lane][r * 14 + j] = acc[r][j];
    }
    __syncthreads();
    if (grp != 0) return;

    #pragma unroll
    for (int g = 0; g < 3; g++) {
        #pragma unroll
        for (int r = 0; r < 2; r++) {
            #pragma unroll
            for (int j = 0; j < 14; j++) {
                ull p = red[g][lane][r * 14 + j];
                float2 pa = *reinterpret_cast<float2*>(&acc[r][j]);
                float2 pb = *reinterpret_cast<float2*>(&p);
                pa.x += pb.x; pa.y += pb.y;
                acc[r][j] = *reinterpret_cast<ull*>(&pa);
            }
        }
    }

    #pragma unroll
    for (int r = 0; r < 2; r++) {
        int h = h0 + r;
        #pragma unroll
        for (int kk = 0; kk < KKc; kk++) {
            float2 oyx = *reinterpret_cast<float2*>(&acc[r][kk]);
            float2 mp  = *reinterpret_cast<float2*>(&acc[r][9 + (kk >> 1)]);
            float mraw = (kk & 1) ? mp.y : mp.x;
            float offy = oyx.x + off_b[2 * kk];
            float offx = oyx.y + off_b[2 * kk + 1];
            float mval = 2.f / (1.f + expf(-(mraw + mod_b[kk])));

            float py = (float)h   - 1.f + (float)(kk / 3) + offy;
            float px = (float)pix - 1.f + (float)(kk % 3) + offx;
            float y0f = floorf(py), x0f = floorf(px);
            float dy = py - y0f, dx = px - x0f;
            int y0 = (int)y0f, x0 = (int)x0f;
            int y1 = y0 + 1,   x1 = x0 + 1;

            float v00 = (y0 >= 0 && y0 < H && x0 >= 0 && x0 < W) ? 1.f : 0.f;
            float v01 = (y0 >= 0 && y0 < H && x1 >= 0 && x1 < W) ? 1.f : 0.f;
            float v10 = (y1 >= 0 && y1 < H && x0 >= 0 && x0 < W) ? 1.f : 0.f;
            float v11 = (y1 >= 0 && y1 < H && x1 >= 0 && x1 < W) ? 1.f : 0.f;

            int y0c = min(max(y0, 0), H - 1), y1c = min(max(y1, 0), H - 1);
            int x0c = min(max(x0, 0), W - 1), x1c = min(max(x1, 0), W - 1);

            float4 wv;
            wv.x = (1.f - dy) * (1.f - dx) * mval * v00;
            wv.y = (1.f - dy) * dx         * mval * v01;
            wv.z = dy         * (1.f - dx) * mval * v10;
            wv.w = dy         * dx         * mval * v11;
            int4 iv;
            iv.x = y0c * W + x0c;  iv.y = y0c * W + x1c;
            iv.z = y1c * W + x0c;  iv.w = y1c * W + x1c;

            size_t t = (((size_t)b * KKc + kk) << 14) + h * W + pix;
            wts[t] = wv;
            idx[t] = iv;
        }
    }
}

// ---------------- deformable im2col: col[c*9+kk][b*HW+hw] ----------------
__global__ void deform_col_kernel(const float* __restrict__ in,
                                  const float4* __restrict__ wts,
                                  const int4* __restrict__ idx,
                                  float* __restrict__ col) {
    int t = blockIdx.x * blockDim.x + threadIdx.x;   // (b*9+kk)*HW + hw
    if (t >= BB * KKc * HW) return;
    int hw = t & (HW - 1);
    int u  = t >> 14;
    int kk = u % KKc;
    int b  = u / KKc;

    float4 w = wts[t];
    int4  ii = idx[t];

    const float* p = in + (size_t)b * C * HW;
    float* o = col + (size_t)kk * NTOT + ((size_t)b << 14) + hw;
    #pragma unroll 4
    for (int c = 0; c < C; c++) {
        float v = p[ii.x] * w.x + p[ii.y] * w.y + p[ii.z] * w.z + p[ii.w] * w.w;
        *o = v;
        p += HW;
        o += (size_t)KKc * NTOT;
    }
}

// ---------------- main GEMM: [96 x 864] @ [864 x 65536], cp.async pipelined -
// Block tile 96 x 128, BK=16, 128 threads, micro tile 6 x 16, f32x2 packed.
__global__ void __launch_bounds__(128, 3) sgemm96_kernel(
    const float* __restrict__ At,     // [864][96] transposed
    const float* __restrict__ Bmat,   // [864][65536]
    float* __restrict__ Out)          // [96][65536]
{
    constexpr int BK = 16;
    constexpr int NCHUNK = CK / BK;   // 54
    __shared__ float As[2][BK][100];  // row pad 100 (400B, 16B-aligned, bank-safe)
    __shared__ float Bs[2][BK][128];

    int tid = threadIdx.x;
    int n0  = blockIdx.x * 128;
    int tx  = tid & 7;                // 8 n-groups of 16
    int ty  = tid >> 3;               // 16 m-groups of 6

    ull acc2[6][8];
    #pragma unroll
    for (int i = 0; i < 6; i++)
        #pragma unroll
        for (int j = 0; j < 8; j++) acc2[i][j] = 0ull;

    // cp.async chunk loader: A 16x96 (24 cp16/row), B 16x128 (32 cp16/row)
    auto load_chunk = [&](int chunk, int buf) {
        int k0 = chunk * BK;
        unsigned aBase = smem_u32(&As[buf][0][0]);
        unsigned bBase = smem_u32(&Bs[buf][0][0]);
        #pragma unroll
        for (int j = 0; j < 3; j++) {          // 384 A-copies
            int e = tid + j * 128;
            int r = e / 24, q = e - r * 24;
            CP16(aBase + (r * 100 + q * 4) * 4,
                 At + (size_t)(k0 + r) * C + q * 4);
        }
        #pragma unroll
        for (int j = 0; j < 4; j++) {          // 512 B-copies
            int e = tid + j * 128;
            int r = e >> 5, s = e & 31;
            CP16(bBase + (r * 128 + s * 4) * 4,
                 Bmat + (size_t)(k0 + r) * NTOT + n0 + s * 4);
        }
    };

    load_chunk(0, 0);
    CP_COMMIT();

    for (int i = 0; i < NCHUNK; i++) {
        if (i + 1 < NCHUNK) load_chunk(i + 1, (i + 1) & 1);
        CP_COMMIT();
        CP_WAIT1();
        __syncthreads();

        int buf = i & 1;
        #pragma unroll
        for (int k = 0; k < BK; k++) {
            float2 a01 = *reinterpret_cast<const float2*>(&As[buf][k][ty * 6]);
            float2 a23 = *reinterpret_cast<const float2*>(&As[buf][k][ty * 6 + 2]);
            float2 a45 = *reinterpret_cast<const float2*>(&As[buf][k][ty * 6 + 4]);
            ull a2[6];
            a2[0] = bcast2(a01.x); a2[1] = bcast2(a01.y);
            a2[2] = bcast2(a23.x); a2[3] = bcast2(a23.y);
            a2[4] = bcast2(a45.x); a2[5] = bcast2(a45.y);

            ull bv[8];
            #pragma unroll
            for (int q = 0; q < 4; q++) {
                float4 bq = *reinterpret_cast<const float4*>(
                    &Bs[buf][k][tx * 16 + q * 4]);
                float2 lo = make_float2(bq.x, bq.y);
                float2 hi = make_float2(bq.z, bq.w);
                bv[2 * q]     = *reinterpret_cast<ull*>(&lo);
                bv[2 * q + 1] = *reinterpret_cast<ull*>(&hi);
            }
            #pragma unroll
            for (int ii = 0; ii < 6; ii++)
                #pragma unroll
                for (int j = 0; j < 8; j++)
                    FMA2(acc2[ii][j], a2[ii], bv[j]);
        }
        __syncthreads();
    }

    #pragma unroll
    for (int i = 0; i < 6; i++) {
        int m = ty * 6 + i;
        float* op = Out + (size_t)m * NTOT + n0 + tx * 16;
        #pragma unroll
        for (int q = 0; q < 4; q++) {
            float2 p0 = *reinterpret_cast<float2*>(&acc2[i][2 * q]);
            float2 p1 = *reinterpret_cast<float2*>(&acc2[i][2 * q + 1]);
            *reinterpret_cast<float4*>(op + q * 4) =
                make_float4(p0.x, p0.y, p1.x, p1.y);
        }
    }
}

// ---------------- batch norm (X layout [c][65536]) ----------------
__global__ void bn_stats_kernel(const float* __restrict__ X,
                                float* __restrict__ stats) {
    int c = blockIdx.x;
    const float* p = X + (size_t)c * NTOT;
    float s = 0.f, s2 = 0.f;
    for (int i = threadIdx.x; i < NTOT; i += blockDim.x) {
        float v = p[i];
        s += v; s2 += v * v;
    }
    __shared__ float sh[256], sh2[256];
    sh[threadIdx.x] = s; sh2[threadIdx.x] = s2;
    __syncthreads();
    for (int st = 128; st > 0; st >>= 1) {
        if (threadIdx.x < st) {
            sh[threadIdx.x]  += sh[threadIdx.x + st];
            sh2[threadIdx.x] += sh2[threadIdx.x + st];
        }
        __syncthreads();
    }
    if (threadIdx.x == 0) {
        float inv = 1.f / (float)NTOT;
        float mean = sh[0] * inv;
        float var  = sh2[0] * inv - mean * mean;
        stats[c]     = mean;
        stats[C + c] = rsqrtf(var + 1e-5f);
    }
}

// read [c][b*HW+hw], write act NCHW
__global__ void bn_lrelu_kernel(const float* __restrict__ X,
                                const float* __restrict__ gam,
                                const float* __restrict__ bet,
                                const float* __restrict__ stats,
                                float* __restrict__ O) {
    int t = blockIdx.x * blockDim.x + threadIdx.x;
    if (t >= C * NTOT) return;
    int c = t >> 16;
    int n = t & (NTOT - 1);
    int b = n >> 14;
    int hw = n & (HW - 1);
    float v = (X[t] - stats[c]) * stats[C + c] * gam[c] + bet[c];
    v = v >= 0.f ? v : 0.1f * v;
    O[(((size_t)b * C + c) << 14) + hw] = v;
}

__global__ void bn_add_kernel(const float* __restrict__ Xres,  // NCHW
                              const float* __restrict__ Hc,    // [c][n]
                              const float* __restrict__ gam,
                              const float* __restrict__ bet,
                              const float* __restrict__ stats,
                              float* __restrict__ O) {          // NCHW
    int t = blockIdx.x * blockDim.x + threadIdx.x;
    if (t >= C * NTOT) return;
    int c = t >> 16;
    int n = t & (NTOT - 1);
    int b = n >> 14;
    int hw = n & (HW - 1);
    float v = (Hc[t] - stats[c]) * stats[C + c] * gam[c] + bet[c];
    size_t oi = (((size_t)b * C + c) << 14) + hw;
    O[oi] = Xres[oi] + v;
}

// ---------------- launch ----------------
extern "C" void kernel_launch(void* const* d_in, const int* in_sizes, int n_in,
                              void* d_out, int out_size) {
    const float* x        = (const float*)d_in[0];
    const float* d1_off_w = (const float*)d_in[1];
    const float* d1_off_b = (const float*)d_in[2];
    const float* d1_mod_w = (const float*)d_in[3];
    const float* d1_mod_b = (const float*)d_in[4];
    const float* d1_w     = (const float*)d_in[5];
    const float* d2_off_w = (const float*)d_in[6];
    const float* d2_off_b = (const float*)d_in[7];
    const float* d2_mod_w = (const float*)d_in[8];
    const float* d2_mod_b = (const float*)d_in[9];
    const float* d2_w     = (const float*)d_in[10];
    const float* bn_g     = (const float*)d_in[11];
    const float* bn_b     = (const float*)d_in[12];
    float* out = (float*)d_out;

    float *p_col, *p_At, *p_conv, *p_act, *p_stats;
    ull* p_wtp; float4* p_wts; int4* p_idx;
    cudaGetSymbolAddress((void**)&p_col,   g_col);
    cudaGetSymbolAddress((void**)&p_At,    g_At);
    cudaGetSymbolAddress((void**)&p_wtp,   g_wtp);
    cudaGetSymbolAddress((void**)&p_wts,   g_wts);
    cudaGetSymbolAddress((void**)&p_idx,   g_idx);
    cudaGetSymbolAddress((void**)&p_conv,  g_conv);
    cudaGetSymbolAddress((void**)&p_act,   g_act);
    cudaGetSymbolAddress((void**)&p_stats, g_stats);

    const int NT = 256;
    const int nCol  = BB * KKc * HW;                 // 589824
    const int nElem = C * NTOT;                      // 6291456
    dim3 off_grid(H, BB);                            // (128, 4)
    int gemm_grid = NTOT / 128;                      // 512

    // ---------- layer 1 ----------
    wprep_kernel<<<(CK * 14 + NT - 1) / NT, NT>>>(d1_off_w, d1_mod_w, p_wtp);
    atrans_kernel<<<(CK * C + NT - 1) / NT, NT>>>(d1_w, p_At);
    offconv_kernel<<<off_grid, 256>>>(p_wtp, x, d1_off_b, d1_mod_b, p_wts, p_idx);
    deform_col_kernel<<<(nCol + NT - 1) / NT, NT>>>(x, p_wts, p_idx, p_col);
    sgemm96_kernel<<<gemm_grid, 128>>>(p_At, p_col, p_conv);
    bn_stats_kernel<<<C, NT>>>(p_conv, p_stats);
    bn_lrelu_kernel<<<(nElem + NT - 1) / NT, NT>>>(p_conv, bn_g, bn_b, p_stats, p_act);

    // ---------- layer 2 ----------
    wprep_kernel<<<(CK * 14 + NT - 1) / NT, NT>>>(d2_off_w, d2_mod_w, p_wtp);
    atrans_kernel<<<(CK * C + NT - 1) / NT, NT>>>(d2_w, p_At);
    offconv_kernel<<<off_grid, 256>>>(p_wtp, p_act, d2_off_b, d2_mod_b, p_wts, p_idx);
    deform_col_kernel<<<(nCol + NT - 1) / NT, NT>>>(p_act, p_wts, p_idx, p_col);
    sgemm96_kernel<<<gemm_grid, 128>>>(p_At, p_col, p_conv);
    bn_stats_kernel<<<C, NT>>>(p_conv, p_stats);
    bn_add_kernel<<<(nElem + NT - 1) / NT, NT>>>(x, p_conv, bn_g, bn_b, p_stats, out);
}

// round 6
// speedup vs baseline: 1.4630x; 1.4630x over previous
#include <cuda_runtime.h>
#include <math.h>
#include <stdint.h>

#define BB 4
#define C 96
#define H 128
#define W 128
#define HW (H*W)          // 16384
#define KKc 9
#define CK (C*KKc)        // 864
#define NPIX (BB*HW)      // 65536 per channel

typedef unsigned long long ull;

// ---------------- device scratch (no allocations allowed) ----------------
__device__ float  g_col [ (size_t)BB * CK * HW ];   // 226.5 MB deform-col
__device__ ull    g_wtp [ CK * 14 ];                // offset|mask weights, opair-packed
__device__ float4 g_wts [ (size_t)BB * KKc * HW ];  // bilinear weights (mask folded)
__device__ int4   g_idx [ (size_t)BB * KKc * HW ];  // bilinear gather indices
__device__ float  g_conv[ (size_t)BB * C * HW ];    // deform-conv output
__device__ float  g_act [ (size_t)BB * C * HW ];    // post BN+leakyrelu
__device__ float  g_stats[ 2 * C ];                 // mean | rstd

// packed f32x2 FMA (FFMA2) — only reachable via explicit PTX on sm_10x
#define FMA2(d, a, b) \
    asm("fma.rn.f32x2 %0, %1, %2, %0;" : "+l"(d) : "l"(a), "l"(b))

__device__ __forceinline__ ull bcast2(float v) {
    ull r;
    unsigned int u = __float_as_uint(v);
    asm("mov.b64 %0, {%1, %1};" : "=l"(r) : "r"(u));
    return r;
}

// ---------------- weight prep: wtp[ck][j] = (w[2j][ck], w[2j+1][ck]) --------
__global__ void wprep_kernel(const float* __restrict__ offw,
                             const float* __restrict__ modw,
                             ull* __restrict__ wtp) {
    int t = blockIdx.x * blockDim.x + threadIdx.x;   // ck*14 + j
    if (t >= CK * 14) return;
    int ck = t / 14, j = t - ck * 14;
    int o0 = 2 * j, o1 = 2 * j + 1;
    float a = (o0 < 18) ? offw[o0 * CK + ck] : modw[(o0 - 18) * CK + ck];
    float b = 0.f;
    if (o1 < 27)
        b = (o1 < 18) ? offw[o1 * CK + ck] : modw[(o1 - 18) * CK + ck];
    float2 p = make_float2(a, b);
    wtp[t] = *reinterpret_cast<ull*>(&p);
}

// ---------------------------------------------------------------------------
// Direct 3x3 conv producing 27 outputs/pixel + bilinear-table epilogue.
// 256 threads = 4 channel-groups (24 ch each) x 64 pixel-columns x 2 rows.
// ---------------------------------------------------------------------------
__global__ void __launch_bounds__(256) offconv_kernel(
    const ull* __restrict__ wtp,     // [864][14] packed pairs
    const float* __restrict__ X,     // [B][C][H][W]
    const float* __restrict__ off_b, // [18]
    const float* __restrict__ mod_b, // [9]
    float4* __restrict__ wts,
    int4*  __restrict__ idx)
{
    __shared__ ull red[3][64][28];

    int tid  = threadIdx.x;
    int lane = tid & 63;
    int grp  = tid >> 6;
    int half = blockIdx.x & 1;
    int h0   = (blockIdx.x >> 1) * 2;
    int b    = blockIdx.y;
    int pix  = half * 64 + lane;

    const float* Xb = X + (size_t)b * C * HW;

    ull acc[2][14];
    #pragma unroll
    for (int r = 0; r < 2; r++)
        #pragma unroll
        for (int j = 0; j < 14; j++) acc[r][j] = 0ull;

    bool xm_ok = (pix > 0);
    bool xp_ok = (pix < W - 1);

    int c0 = grp * 24;
    for (int ci = 0; ci < 24; ci++) {
        int c = c0 + ci;
        ull tb[4][3];
        #pragma unroll
        for (int rr = 0; rr < 4; rr++) {
            int y = h0 - 1 + rr;
            bool yok = (y >= 0) && (y < H);
            const float* row = Xb + (size_t)c * HW + y * W + pix;
            float vm = (yok && xm_ok) ? row[-1] : 0.f;
            float v0 = yok ? row[0] : 0.f;
            float vp = (yok && xp_ok) ? row[1] : 0.f;
            tb[rr][0] = bcast2(vm);
            tb[rr][1] = bcast2(v0);
            tb[rr][2] = bcast2(vp);
        }
        const ulonglong2* wrow =
            reinterpret_cast<const ulonglong2*>(wtp + (size_t)c * 9 * 14);
        #pragma unroll
        for (int ky = 0; ky < 3; ky++) {
            #pragma unroll
            for (int kx = 0; kx < 3; kx++) {
                int tap = ky * 3 + kx;
                ull t0 = tb[ky][kx];
                ull t1 = tb[ky + 1][kx];
                #pragma unroll
                for (int j2 = 0; j2 < 7; j2++) {
                    ulonglong2 wv = wrow[tap * 7 + j2];
                    FMA2(acc[0][2 * j2],     wv.x, t0);
                    FMA2(acc[1][2 * j2],     wv.x, t1);
                    FMA2(acc[0][2 * j2 + 1], wv.y, t0);
                    FMA2(acc[1][2 * j2 + 1], wv.y, t1);
                }
            }
        }
    }

    if (grp > 0) {
        #pragma unroll
        for (int r = 0; r < 2; r++)
            #pragma unroll
            for (int j = 0; j < 14; j++)
                red[grp - 1][lane][r * 14 + j] = acc[r][j];
    }
    __syncthreads();
    if (grp != 0) return;

    #pragma unroll
    for (int g = 0; g < 3; g++) {
        #pragma unroll
        for (int r = 0; r < 2; r++) {
            #pragma unroll
            for (int j = 0; j < 14; j++) {
                ull p = red[g][lane][r * 14 + j];
                float2 pa = *reinterpret_cast<float2*>(&acc[r][j]);
                float2 pb = *reinterpret_cast<float2*>(&p);
                pa.x += pb.x; pa.y += pb.y;
                acc[r][j] = *reinterpret_cast<ull*>(&pa);
            }
        }
    }

    #pragma unroll
    for (int r = 0; r < 2; r++) {
        int h = h0 + r;
        #pragma unroll
        for (int kk = 0; kk < KKc; kk++) {
            float2 oyx = *reinterpret_cast<float2*>(&acc[r][kk]);
            float2 mp  = *reinterpret_cast<float2*>(&acc[r][9 + (kk >> 1)]);
            float mraw = (kk & 1) ? mp.y : mp.x;
            float offy = oyx.x + off_b[2 * kk];
            float offx = oyx.y + off_b[2 * kk + 1];
            float mval = 2.f / (1.f + expf(-(mraw + mod_b[kk])));

            float py = (float)h   - 1.f + (float)(kk / 3) + offy;
            float px = (float)pix - 1.f + (float)(kk % 3) + offx;
            float y0f = floorf(py), x0f = floorf(px);
            float dy = py - y0f, dx = px - x0f;
            int y0 = (int)y0f, x0 = (int)x0f;
            int y1 = y0 + 1,   x1 = x0 + 1;

            float v00 = (y0 >= 0 && y0 < H && x0 >= 0 && x0 < W) ? 1.f : 0.f;
            float v01 = (y0 >= 0 && y0 < H && x1 >= 0 && x1 < W) ? 1.f : 0.f;
            float v10 = (y1 >= 0 && y1 < H && x0 >= 0 && x0 < W) ? 1.f : 0.f;
            float v11 = (y1 >= 0 && y1 < H && x1 >= 0 && x1 < W) ? 1.f : 0.f;

            int y0c = min(max(y0, 0), H - 1), y1c = min(max(y1, 0), H - 1);
            int x0c = min(max(x0, 0), W - 1), x1c = min(max(x1, 0), W - 1);

            float4 wv;
            wv.x = (1.f - dy) * (1.f - dx) * mval * v00;
            wv.y = (1.f - dy) * dx         * mval * v01;
            wv.z = dy         * (1.f - dx) * mval * v10;
            wv.w = dy         * dx         * mval * v11;
            int4 iv;
            iv.x = y0c * W + x0c;  iv.y = y0c * W + x1c;
            iv.z = y1c * W + x0c;  iv.w = y1c * W + x1c;

            size_t t = (((size_t)b * KKc + kk) << 14) + h * W + pix;
            wts[t] = wv;
            idx[t] = iv;
        }
    }
}

// ---------------- deformable im2col via precomputed tables ----------------
__global__ void deform_col_kernel(const float* __restrict__ in,
                                  const float4* __restrict__ wts,
                                  const int4* __restrict__ idx,
                                  float* __restrict__ col) {
    int t = blockIdx.x * blockDim.x + threadIdx.x;   // (b*9+kk)*HW + hw
    if (t >= BB * KKc * HW) return;
    int hw = t & (HW - 1);
    int u  = t >> 14;
    int kk = u % KKc;
    int b  = u / KKc;

    float4 w = wts[t];
    int4  ii = idx[t];

    const float* p = in + (size_t)b * C * HW;
    float* o = col + ((size_t)b * CK + kk) * HW + hw;
    #pragma unroll 4
    for (int c = 0; c < C; c++) {
        float v = p[ii.x] * w.x + p[ii.y] * w.y + p[ii.z] * w.z + p[ii.w] * w.w;
        *o = v;
        p += HW;
        o += (size_t)KKc * HW;
    }
}

// ---------------- main GEMM: 96 x 864 x 16384/batch, f32x2 packed ----------
// BK=32, register-staged double buffering (LDG latency hidden under compute).
__global__ void __launch_bounds__(256, 2) sgemm96_kernel(
    const float* __restrict__ A,      // [96][864]
    const float* __restrict__ Bmat,   // [B][864][HW]
    float* __restrict__ Out)          // [B][96][HW]
{
    constexpr int BK = 32, BN = 128, BM = 96;
    constexpr int NCHUNK = CK / BK;    // 27
    __shared__ float As[BK][BM + 2];   // row = 98 floats
    __shared__ float Bs[BK][BN];

    int tid = threadIdx.x;
    int b   = blockIdx.y;
    int n0  = blockIdx.x * BN;
    int tx  = tid & 15;
    int ty  = tid >> 4;

    const float* Bb = Bmat + (size_t)b * CK * HW;

    ull acc2[6][4];
    #pragma unroll
    for (int i = 0; i < 6; i++)
        #pragma unroll
        for (int j = 0; j < 4; j++) acc2[i][j] = 0ull;

    int br = tid >> 3;           // 0..31  (B row)
    int bq = tid & 7;            // 0..7   (col group)
    int am = (tid * 3) >> 3;     // == e>>3 pattern below
    // A-staging indices: 3 elements e = tid + i*256
    //   m = e>>3 (0..95), kq = e&7 (0..7)

    float4 ra[3], rb[4];

    auto gload = [&](int k0) {
        #pragma unroll
        for (int i = 0; i < 3; i++) {
            int e = tid + i * 256;
            int m  = e >> 3;
            int kq = e & 7;
            ra[i] = *reinterpret_cast<const float4*>(&A[m * CK + k0 + kq * 4]);
        }
        #pragma unroll
        for (int j = 0; j < 4; j++)
            rb[j] = *reinterpret_cast<const float4*>(
                Bb + (size_t)(k0 + br) * HW + n0 + bq * 4 + j * 32);
    };
    auto sstore = [&]() {
        #pragma unroll
        for (int i = 0; i < 3; i++) {
            int e = tid + i * 256;
            int m  = e >> 3;
            int kq = e & 7;
            As[kq * 4 + 0][m] = ra[i].x;
            As[kq * 4 + 1][m] = ra[i].y;
            As[kq * 4 + 2][m] = ra[i].z;
            As[kq * 4 + 3][m] = ra[i].w;
        }
        #pragma unroll
        for (int j = 0; j < 4; j++)
            *reinterpret_cast<float4*>(&Bs[br][bq * 4 + j * 32]) = rb[j];
    };

    gload(0);
    sstore();
    __syncthreads();

    for (int ch = 0; ch < NCHUNK; ch++) {
        if (ch + 1 < NCHUNK) gload((ch + 1) * BK);   // overlap with compute

        #pragma unroll
        for (int k = 0; k < BK; k++) {
            float2 a01 = *reinterpret_cast<const float2*>(&As[k][ty * 6]);
            float2 a23 = *reinterpret_cast<const float2*>(&As[k][ty * 6 + 2]);
            float2 a45 = *reinterpret_cast<const float2*>(&As[k][ty * 6 + 4]);
            ull a2[6];
            a2[0] = bcast2(a01.x); a2[1] = bcast2(a01.y);
            a2[2] = bcast2(a23.x); a2[3] = bcast2(a23.y);
            a2[4] = bcast2(a45.x); a2[5] = bcast2(a45.y);

            float4 bl = *reinterpret_cast<const float4*>(&Bs[k][tx * 4]);
            float4 bh = *reinterpret_cast<const float4*>(&Bs[k][64 + tx * 4]);
            float2 q0 = make_float2(bl.x, bl.y);
            float2 q1 = make_float2(bl.z, bl.w);
            float2 q2 = make_float2(bh.x, bh.y);
            float2 q3 = make_float2(bh.z, bh.w);
            ull b0 = *reinterpret_cast<ull*>(&q0);
            ull b1 = *reinterpret_cast<ull*>(&q1);
            ull b2v = *reinterpret_cast<ull*>(&q2);
            ull b3 = *reinterpret_cast<ull*>(&q3);

            #pragma unroll
            for (int i = 0; i < 6; i++) {
                FMA2(acc2[i][0], a2[i], b0);
                FMA2(acc2[i][1], a2[i], b1);
                FMA2(acc2[i][2], a2[i], b2v);
                FMA2(acc2[i][3], a2[i], b3);
            }
        }
        __syncthreads();
        if (ch + 1 < NCHUNK) {
            sstore();
            __syncthreads();
        }
    }

    #pragma unroll
    for (int i = 0; i < 6; i++) {
        int m = ty * 6 + i;
        float* op = Out + ((size_t)b * BM + m) * HW + n0 + tx * 4;
        float2 p0 = *reinterpret_cast<float2*>(&acc2[i][0]);
        float2 p1 = *reinterpret_cast<float2*>(&acc2[i][1]);
        float2 p2 = *reinterpret_cast<float2*>(&acc2[i][2]);
        float2 p3 = *reinterpret_cast<float2*>(&acc2[i][3]);
        *reinterpret_cast<float4*>(op)      = make_float4(p0.x, p0.y, p1.x, p1.y);
        *reinterpret_cast<float4*>(op + 64) = make_float4(p2.x, p2.y, p3.x, p3.y);
    }
    (void)am;
}

// ---------------- batch norm ----------------
__global__ void bn_stats_kernel(const float* __restrict__ X,
                                float* __restrict__ stats) {
    int c = blockIdx.x;
    float s = 0.f, s2 = 0.f;
    for (int i = threadIdx.x; i < NPIX; i += blockDim.x) {
        int b  = i >> 14;
        int hw = i & (HW - 1);
        float v = X[((size_t)b * C + c) * HW + hw];
        s  += v;
        s2 += v * v;
    }
    __shared__ float sh[256], sh2[256];
    sh[threadIdx.x] = s; sh2[threadIdx.x] = s2;
    __syncthreads();
    for (int st = 128; st > 0; st >>= 1) {
        if (threadIdx.x < st) {
            sh[threadIdx.x]  += sh[threadIdx.x + st];
            sh2[threadIdx.x] += sh2[threadIdx.x + st];
        }
        __syncthreads();
    }
    if (threadIdx.x == 0) {
        float inv = 1.f / (float)NPIX;
        float mean = sh[0] * inv;
        float var  = sh2[0] * inv - mean * mean;
        stats[c]     = mean;
        stats[C + c] = rsqrtf(var + 1e-5f);
    }
}

__global__ void bn_lrelu_kernel(const float* __restrict__ X,
                                const float* __restrict__ gam,
                                const float* __restrict__ bet,
                                const float* __restrict__ stats,
                                float* __restrict__ O) {
    int idx = blockIdx.x * blockDim.x + threadIdx.x;
    if (idx >= BB * C * HW) return;
    int c = (idx / HW) % C;
    float v = (X[idx] - stats[c]) * stats[C + c] * gam[c] + bet[c];
    O[idx] = v >= 0.f ? v : 0.1f * v;
}

__global__ void bn_add_kernel(const float* __restrict__ Xres,
                              const float* __restrict__ Hc,
                              const float* __restrict__ gam,
                              const float* __restrict__ bet,
                              const float* __restrict__ stats,
                              float* __restrict__ O) {
    int idx = blockIdx.x * blockDim.x + threadIdx.x;
    if (idx >= BB * C * HW) return;
    int c = (idx / HW) % C;
    float v = (Hc[idx] - stats[c]) * stats[C + c] * gam[c] + bet[c];
    O[idx] = Xres[idx] + v;
}

// ---------------- launch ----------------
extern "C" void kernel_launch(void* const* d_in, const int* in_sizes, int n_in,
                              void* d_out, int out_size) {
    const float* x        = (const float*)d_in[0];
    const float* d1_off_w = (const float*)d_in[1];
    const float* d1_off_b = (const float*)d_in[2];
    const float* d1_mod_w = (const float*)d_in[3];
    const float* d1_mod_b = (const float*)d_in[4];
    const float* d1_w     = (const float*)d_in[5];
    const float* d2_off_w = (const float*)d_in[6];
    const float* d2_off_b = (const float*)d_in[7];
    const float* d2_mod_w = (const float*)d_in[8];
    const float* d2_mod_b = (const float*)d_in[9];
    const float* d2_w     = (const float*)d_in[10];
    const float* bn_g     = (const float*)d_in[11];
    const float* bn_b     = (const float*)d_in[12];
    float* out = (float*)d_out;

    float *p_col, *p_conv, *p_act, *p_stats;
    ull* p_wtp; float4* p_wts; int4* p_idx;
    cudaGetSymbolAddress((void**)&p_col,   g_col);
    cudaGetSymbolAddress((void**)&p_wtp,   g_wtp);
    cudaGetSymbolAddress((void**)&p_wts,   g_wts);
    cudaGetSymbolAddress((void**)&p_idx,   g_idx);
    cudaGetSymbolAddress((void**)&p_conv,  g_conv);
    cudaGetSymbolAddress((void**)&p_act,   g_act);
    cudaGetSymbolAddress((void**)&p_stats, g_stats);

    const int NT = 256;
    const int nCol  = BB * KKc * HW;                 // 589824
    const int nElem = BB * C * HW;                   // 6291456
    dim3 gemm_grid(HW / 128, BB);                    // (128, 4)
    dim3 off_grid(H, BB);                            // (128, 4)

    // ---------- layer 1 ----------
    wprep_kernel<<<(CK * 14 + NT - 1) / NT, NT>>>(d1_off_w, d1_mod_w, p_wtp);
    offconv_kernel<<<off_grid, 256>>>(p_wtp, x, d1_off_b, d1_mod_b, p_wts, p_idx);
    deform_col_kernel<<<(nCol + NT - 1) / NT, NT>>>(x, p_wts, p_idx, p_col);
    sgemm96_kernel<<<gemm_grid, NT>>>(d1_w, p_col, p_conv);
    bn_stats_kernel<<<C, NT>>>(p_conv, p_stats);
    bn_lrelu_kernel<<<(nElem + NT - 1) / NT, NT>>>(p_conv, bn_g, bn_b, p_stats, p_act);

    // ---------- layer 2 ----------
    wprep_kernel<<<(CK * 14 + NT - 1) / NT, NT>>>(d2_off_w, d2_mod_w, p_wtp);
    offconv_kernel<<<off_grid, 256>>>(p_wtp, p_act, d2_off_b, d2_mod_b, p_wts, p_idx);
    deform_col_kernel<<<(nCol + NT - 1) / NT, NT>>>(p_act, p_wts, p_idx, p_col);
    sgemm96_kernel<<<gemm_grid, NT>>>(d2_w, p_col, p_conv);
    bn_stats_kernel<<<C, NT>>>(p_conv, p_stats);
    bn_add_kernel<<<(nElem + NT - 1) / NT, NT>>>(x, p_conv, bn_g, bn_b, p_stats, out);
}